// round 1
// baseline (speedup 1.0000x reference)
#include <cuda_runtime.h>
#include <cstdint>

// KV-cache concat: out = [keys | values]
//   keys   = concat(key_cache[B,H,S,D],   key_states[B,H,1,D],   dim=-2)
//   values = concat(value_cache[B,H,S,D], value_states[B,H,1,D], dim=-2)
// B=8, H=32, S=4096, D=128, f32.
//
// Pure streaming copy. float4-vectorized, fully coalesced.
// Grid: x covers one (b,h) slab of (S+1)*D/4 float4s, y = b*H+h, z = tensor.

static constexpr int B = 8;
static constexpr int H = 32;
static constexpr int S = 4096;
static constexpr int D = 128;
static constexpr int D4 = D / 4;                 // 32 float4 per row
static constexpr int SLAB4 = (S + 1) * D4;       // 131104 float4 per (b,h) per tensor
static constexpr long long TENSOR4 = (long long)B * H * SLAB4;  // float4 per output tensor

__global__ __launch_bounds__(256)
void kvcache_concat_kernel(const float4* __restrict__ key_cache,
                           const float4* __restrict__ value_cache,
                           const float4* __restrict__ key_states,
                           const float4* __restrict__ value_states,
                           float4* __restrict__ out)
{
    const int i = blockIdx.x * blockDim.x + threadIdx.x;  // float4 index within slab
    if (i >= SLAB4) return;

    const int bh = blockIdx.y;       // 0..B*H-1
    const int t  = blockIdx.z;       // 0 = keys, 1 = values

    const float4* __restrict__ cache  = t ? value_cache  : key_cache;
    const float4* __restrict__ states = t ? value_states : key_states;

    const int s    = i >> 5;         // row within slab (0..4096)
    const int lane = i & 31;         // float4 within row

    float4 v;
    if (s < S) {
        v = cache[((long long)bh * S + s) * D4 + lane];
    } else {
        v = states[(long long)bh * D4 + lane];
    }

    out[(long long)t * TENSOR4 + (long long)bh * SLAB4 + i] = v;
}

extern "C" void kernel_launch(void* const* d_in, const int* in_sizes, int n_in,
                              void* d_out, int out_size)
{
    const float4* key_cache    = (const float4*)d_in[0];
    const float4* value_cache  = (const float4*)d_in[1];
    const float4* key_states   = (const float4*)d_in[2];
    const float4* value_states = (const float4*)d_in[3];
    float4* out = (float4*)d_out;

    dim3 block(256);
    dim3 grid((SLAB4 + 255) / 256, B * H, 2);   // (513, 256, 2)
    kvcache_concat_kernel<<<grid, block>>>(key_cache, value_cache,
                                           key_states, value_states, out);
}

// round 2
// speedup vs baseline: 1.0350x; 1.0350x over previous
#include <cuda_runtime.h>
#include <cstdint>

// KV-cache concat: out = [keys | values]
//   keys   = concat(key_cache[B,H,S,D],   key_states[B,H,1,D],   dim=-2)
//   values = concat(value_cache[B,H,S,D], value_states[B,H,1,D], dim=-2)
// B=8, H=32, S=4096, D=128, f32. Pure HBM-bound streaming copy.
//
// R2: branch-free dense bulk mapping (S*D4 = 2^17 -> out = j + (j>>17)*32),
// 4x front-batched float4 per thread (MLP=4), streaming cache hints,
// exact grid (no guards), tiny separate kernel for the 1-row state appends.

static constexpr int B = 8;
static constexpr int H = 32;
static constexpr int S = 4096;
static constexpr int D = 128;
static constexpr int D4 = D / 4;                        // 32 float4 per row
static constexpr int SLAB4 = (S + 1) * D4;              // 131104 float4 per (b,h)
static constexpr long long CACHE4 = (long long)B * H * S * D4;   // 33554432 (= 2^25)
static constexpr long long TENSOR4 = (long long)B * H * SLAB4;   // float4 per out tensor

static constexpr int TPB = 256;
static constexpr int UNROLL = 4;
static constexpr int BLOCKS_PER_TENSOR = (int)(CACHE4 / (TPB * UNROLL));  // 32768 exact

// Bulk: copy the two caches into their (gapped) positions in out.
__global__ __launch_bounds__(TPB)
void kv_bulk_kernel(const float4* __restrict__ key_cache,
                    const float4* __restrict__ value_cache,
                    float4* __restrict__ out)
{
    const int t = blockIdx.y;                       // 0 = keys, 1 = values
    const float4* __restrict__ src = t ? value_cache : key_cache;
    float4* __restrict__ dst = out + (long long)t * TENSOR4;

    long long j0 = (long long)blockIdx.x * (TPB * UNROLL) + threadIdx.x;

    // Front-batched loads (MLP = 4), streaming (evict-first) reads.
    float4 v[UNROLL];
#pragma unroll
    for (int u = 0; u < UNROLL; u++)
        v[u] = __ldcs(src + (j0 + (long long)u * TPB));

    // Streaming stores. out index = j + (bh<<5), bh = j>>17 (S*D4 = 2^17).
#pragma unroll
    for (int u = 0; u < UNROLL; u++) {
        long long j = j0 + (long long)u * TPB;
        __stcs(dst + (j + ((j >> 17) << 5)), v[u]);
    }
}

// States: append the single new row per (b,h) for both tensors.
// 2 tensors * 256 bh * 32 float4 = 16384 threads.
__global__ __launch_bounds__(TPB)
void kv_state_kernel(const float4* __restrict__ key_states,
                     const float4* __restrict__ value_states,
                     float4* __restrict__ out)
{
    const int i = blockIdx.x * TPB + threadIdx.x;   // 0..16383
    const int t    = i >> 13;                       // 0/1
    const int bh   = (i >> 5) & 255;                // 0..255
    const int lane = i & 31;                        // 0..31

    const float4* __restrict__ states = t ? value_states : key_states;
    float4 v = __ldcs(states + ((long long)bh * D4 + lane));
    out[(long long)t * TENSOR4 + (long long)bh * SLAB4 + (long long)S * D4 + lane] = v;
}

extern "C" void kernel_launch(void* const* d_in, const int* in_sizes, int n_in,
                              void* d_out, int out_size)
{
    const float4* key_cache    = (const float4*)d_in[0];
    const float4* value_cache  = (const float4*)d_in[1];
    const float4* key_states   = (const float4*)d_in[2];
    const float4* value_states = (const float4*)d_in[3];
    float4* out = (float4*)d_out;

    dim3 bulk_grid(BLOCKS_PER_TENSOR, 2, 1);        // (32768, 2)
    kv_bulk_kernel<<<bulk_grid, TPB>>>(key_cache, value_cache, out);

    kv_state_kernel<<<16384 / TPB, TPB>>>(key_states, value_states, out);
}

// round 3
// speedup vs baseline: 1.0443x; 1.0090x over previous
#include <cuda_runtime.h>
#include <cstdint>

// KV-cache concat: out = [keys | values]
//   keys   = concat(key_cache[B,H,S,D],   key_states[B,H,1,D],   dim=-2)
//   values = concat(value_cache[B,H,S,D], value_states[B,H,1,D], dim=-2)
// B=8, H=32, S=4096, D=128, f32. Pure HBM-bound streaming copy.
//
// R3: single fused kernel. Bulk copy branch-free (S*D4 = 2^17 ->
// out = j + (j>>17)*32), UNROLL=8 front-batched float4 (MLP=8), streaming
// cache hints, exact grid. The 1-row state appends are folded into the
// first 32 blocks of each tensor (one extra float4 per thread there),
// eliminating the second 5.8us launch.

static constexpr int B = 8;
static constexpr int H = 32;
static constexpr int S = 4096;
static constexpr int D = 128;
static constexpr int D4 = D / 4;                        // 32 float4 per row
static constexpr int SLAB4 = (S + 1) * D4;              // 131104 float4 per (b,h)
static constexpr long long CACHE4 = (long long)B * H * S * D4;   // 2^25
static constexpr long long TENSOR4 = (long long)B * H * SLAB4;   // float4 per out tensor

static constexpr int TPB = 256;
static constexpr int UNROLL = 8;
static constexpr int BLOCKS_PER_TENSOR = (int)(CACHE4 / (TPB * UNROLL));  // 16384 exact
static constexpr int STATE4_PER_TENSOR = B * H * D4;    // 8192 float4
static constexpr int STATE_BLOCKS = STATE4_PER_TENSOR / TPB;  // 32

__global__ __launch_bounds__(TPB)
void kv_concat_fused_kernel(const float4* __restrict__ key_cache,
                            const float4* __restrict__ value_cache,
                            const float4* __restrict__ key_states,
                            const float4* __restrict__ value_states,
                            float4* __restrict__ out)
{
    const int t = blockIdx.y;                       // 0 = keys, 1 = values
    const float4* __restrict__ src = t ? value_cache : key_cache;
    float4* __restrict__ dst = out + (long long)t * TENSOR4;

    const long long j0 = (long long)blockIdx.x * (TPB * UNROLL) + threadIdx.x;

    // Front-batched loads (MLP = 8), streaming (evict-first) reads.
    float4 v[UNROLL];
#pragma unroll
    for (int u = 0; u < UNROLL; u++)
        v[u] = __ldcs(src + (j0 + (long long)u * TPB));

    // Streaming stores. out index = j + (bh<<5), bh = j>>17 (S*D4 = 2^17).
#pragma unroll
    for (int u = 0; u < UNROLL; u++) {
        long long j = j0 + (long long)u * TPB;
        __stcs(dst + (j + ((j >> 17) << 5)), v[u]);
    }

    // Fused state append: first STATE_BLOCKS blocks of each tensor write the
    // single new row per (b,h). One extra float4 per thread here (2 MB total).
    if (blockIdx.x < STATE_BLOCKS) {
        const int i = blockIdx.x * TPB + threadIdx.x;   // 0..8191
        const int bh   = i >> 5;                        // 0..255
        const int lane = i & 31;                        // 0..31
        const float4* __restrict__ states = t ? value_states : key_states;
        float4 sv = __ldcs(states + ((long long)bh * D4 + lane));
        dst[(long long)bh * SLAB4 + (long long)S * D4 + lane] = sv;
    }
}

extern "C" void kernel_launch(void* const* d_in, const int* in_sizes, int n_in,
                              void* d_out, int out_size)
{
    const float4* key_cache    = (const float4*)d_in[0];
    const float4* value_cache  = (const float4*)d_in[1];
    const float4* key_states   = (const float4*)d_in[2];
    const float4* value_states = (const float4*)d_in[3];
    float4* out = (float4*)d_out;

    dim3 grid(BLOCKS_PER_TENSOR, 2, 1);             // (16384, 2)
    kv_concat_fused_kernel<<<grid, TPB>>>(key_cache, value_cache,
                                          key_states, value_states, out);
}